// round 16
// baseline (speedup 1.0000x reference)
#include <cuda_runtime.h>
#include <cuda_bf16.h>
#include <mma.h>
#include <math.h>
#include <stdint.h>

using namespace nvcuda;

#define HW   1024
#define DM   64
#define DS   16
#define NV   25
#define TIN  4
#define MAXS 8

// ---------------- scratch (static device globals; no allocation) ----------------
__device__ __align__(128) float g_u[TIN * HW * DM];
__device__ __align__(128) float g_e1[TIN * HW * DM];
__device__ __align__(128) float g_cc[TIN * HW * 96];
__device__ __align__(128) float g_bpack[96];
__device__ __align__(128) float g_A[DS * DM];
__device__ __align__(128) float g_rA[DS * DM];
__device__ int   g_uniA;
// bf16 hi/lo weights in [tap][ic][oc] layout per conv-set
#define WOFF_E   0
#define WOFF_C   36864
#define WOFF_D1  92160
#define WOFF_D2  129024
#define WTOT     165888
__device__ __align__(128) __nv_bfloat16 g_wfH[WTOT];
__device__ __align__(128) __nv_bfloat16 g_wfL[WTOT];
// history fields
__device__ __align__(128) float g_ef[MAXS * HW * DM * 2];
__device__ __align__(128) float g_dl[MAXS * HW * DM];
__device__ __align__(128) float g_uf[MAXS * HW * DM];
__device__ __align__(128) float g_Bf[MAXS * HW * DS];
__device__ __align__(128) float g_ymax[HW * DM];
__device__ __align__(128) float g_d1[HW * DM];
__device__ __align__(128) float g_d2[HW * DM];

// ---------------- pack: bf16 hi/lo weights [tap][ic][oc] + bias + A ----------------
__global__ void pack_all(const float* __restrict__ wd, const float* __restrict__ bd,
                         const float* __restrict__ wB, const float* __restrict__ wC,
                         const float* __restrict__ logA,
                         const float* __restrict__ ew2, const float* __restrict__ dw1,
                         const float* __restrict__ dw2)
{
    int k = blockIdx.x * 256 + threadIdx.x;
    if (k < WTOT) {
        float v;
        if (k < WOFF_C) {                     // enc2: [tap][ic][64]
            int tap = k / 4096, r2 = k & 4095, ic = r2 >> 6, oc = r2 & 63;
            v = ew2[oc * 576 + ic * 9 + tap];
        } else if (k < WOFF_D1) {             // cc: [tap][ic][96]
            int k2 = k - WOFF_C;
            int tap = k2 / 6144, r2 = k2 % 6144, ic = r2 / 96, oc = r2 % 96;
            v = (oc < 64) ? wd[oc * 576 + ic * 9 + tap]
              : (oc < 80) ? wB[(oc - 64) * 576 + ic * 9 + tap]
                          : wC[(oc - 80) * 576 + ic * 9 + tap];
        } else if (k < WOFF_D2) {             // dec1
            int k2 = k - WOFF_D1;
            int tap = k2 / 4096, r2 = k2 & 4095, ic = r2 >> 6, oc = r2 & 63;
            v = dw1[oc * 576 + ic * 9 + tap];
        } else {                              // dec2
            int k2 = k - WOFF_D2;
            int tap = k2 / 4096, r2 = k2 & 4095, ic = r2 >> 6, oc = r2 & 63;
            v = dw2[oc * 576 + ic * 9 + tap];
        }
        __nv_bfloat16 h = __float2bfloat16(v);
        g_wfH[k] = h;
        g_wfL[k] = __float2bfloat16(v - __bfloat162float(h));
    }
    if (k < DM)       g_bpack[k] = bd[k];
    else if (k < 96)  g_bpack[k] = 0.f;
    if (k < DS * DM) {
        int n = k >> 6, d = k & 63;
        float a = -expf(logA[d * DS + n]);
        g_A[k] = a;
        g_rA[k] = 1.f / a;
    }
}

__global__ void check_uni(const float* __restrict__ logA)
{
    __shared__ int ok;
    if (threadIdx.x == 0) ok = 1;
    __syncthreads();
    bool bad = false;
    for (int i = threadIdx.x; i < DM * DS; i += 256)
        if (logA[i] != logA[(i / DS) * DS]) bad = true;
    if (bad) atomicAnd(&ok, 0);
    __syncthreads();
    if (threadIdx.x == 0) g_uniA = ok;
}

// ---------------- WMMA bf16-split implicit-GEMM circular conv, IC=64 ----------------
// D[64px, OC] = sum over 9 taps A_t[64,64] * W_t[64,OC], 3-pass hi/lo split in fp32 acc.
// Block = 256 thr = 8 warps (4 m-tiles x 2 n-groups). grid = (16, 1, z).
#define XS_H    0
#define XS_L    16384
#define ABUF_H(b) (32768 + (b) * 8192)
#define ABUF_L(b) (49152 + (b) * 8192)
#define OUT_OFF 65536
#define SMW     90112

__device__ __forceinline__ void split2(float v, __nv_bfloat16& h, __nv_bfloat16& l) {
    h = __float2bfloat16(v);
    l = __float2bfloat16(v - __bfloat162float(h));
}

template <int OC, bool RELU>
__global__ __launch_bounds__(256) void conv_wmma(const float* __restrict__ x,
                                                 const __nv_bfloat16* __restrict__ wH,
                                                 const __nv_bfloat16* __restrict__ wL,
                                                 const float* __restrict__ bias,
                                                 float* __restrict__ y)
{
    extern __shared__ __align__(128) char sm[];
    __nv_bfloat16* xsH = (__nv_bfloat16*)(sm + XS_H);
    __nv_bfloat16* xsL = (__nv_bfloat16*)(sm + XS_L);
    float* outb = (float*)(sm + OUT_OFF);
    const int tid = threadIdx.x;
    const int wid = tid >> 5;
    x += (size_t)blockIdx.z * HW * DM;
    y += (size_t)blockIdx.z * (size_t)HW * OC;
    const int r0 = blockIdx.x * 2;     // 2 image rows = 64 px

    // stage rows r0-1..r0+2 as split bf16, layout [lr][c][ic]
    const float4* x4 = (const float4*)x;
    for (int k = tid; k < 4 * 32 * 16; k += 256) {
        int lr = k >> 9, rem = k & 511, c = rem >> 4, q = rem & 15;
        int row = (r0 - 1 + lr) & 31;
        float4 v = x4[(((row << 5) + c) << 4) + q];
        __nv_bfloat16 h0, h1, h2, h3, l0, l1, l2, l3;
        split2(v.x, h0, l0); split2(v.y, h1, l1);
        split2(v.z, h2, l2); split2(v.w, h3, l3);
        int off = (lr * 32 + c) * 64 + q * 4;
        __nv_bfloat162* dh = (__nv_bfloat162*)(xsH + off);
        __nv_bfloat162* dl = (__nv_bfloat162*)(xsL + off);
        dh[0] = __nv_bfloat162(h0, h1); dh[1] = __nv_bfloat162(h2, h3);
        dl[0] = __nv_bfloat162(l0, l1); dl[1] = __nv_bfloat162(l2, l3);
    }
    __syncthreads();

    auto copy_tap = [&](int tap, int buf) {
        int tr = tap / 3, tc = tap - tr * 3;
        __nv_bfloat16* AH = (__nv_bfloat16*)(sm + ABUF_H(buf));
        __nv_bfloat16* AL = (__nv_bfloat16*)(sm + ABUF_L(buf));
        for (int k = tid; k < 512; k += 256) {
            int m = k >> 3, q = k & 7;
            int lr = (m >> 5) + tr;
            int sc = ((m & 31) + tc + 31) & 31;
            int so = (lr * 32 + sc) * 64 + q * 8;
            int dof = m * 64 + q * 8;
            *(uint4*)(AH + dof) = *(const uint4*)(xsH + so);
            *(uint4*)(AL + dof) = *(const uint4*)(xsL + so);
        }
    };

    constexpr int NPW = OC / 32;       // n-tiles per warp (2 or 3)
    const int mt = wid >> 1;           // m-tile 0..3
    const int ng = wid & 1;            // n-group
    wmma::fragment<wmma::accumulator, 16, 16, 16, float> acc[NPW];
#pragma unroll
    for (int j = 0; j < NPW; j++) wmma::fill_fragment(acc[j], 0.0f);

    copy_tap(0, 0);
    __syncthreads();
#pragma unroll 1
    for (int t = 0; t < 9; t++) {
        int b = t & 1;
        if (t + 1 < 9) copy_tap(t + 1, b ^ 1);
        const __nv_bfloat16* AH = (const __nv_bfloat16*)(sm + ABUF_H(b));
        const __nv_bfloat16* AL = (const __nv_bfloat16*)(sm + ABUF_L(b));
#pragma unroll
        for (int ks = 0; ks < 4; ks++) {
            wmma::fragment<wmma::matrix_a, 16, 16, 16, __nv_bfloat16, wmma::row_major> ah, al;
            wmma::load_matrix_sync(ah, AH + mt * 16 * 64 + ks * 16, 64);
            wmma::load_matrix_sync(al, AL + mt * 16 * 64 + ks * 16, 64);
#pragma unroll
            for (int j = 0; j < NPW; j++) {
                int nb = (ng * NPW + j) * 16;
                wmma::fragment<wmma::matrix_b, 16, 16, 16, __nv_bfloat16, wmma::row_major> bh, bl;
                size_t wo = (size_t)(t * 64 + ks * 16) * OC + nb;
                wmma::load_matrix_sync(bh, wH + wo, OC);
                wmma::load_matrix_sync(bl, wL + wo, OC);
                wmma::mma_sync(acc[j], ah, bh, acc[j]);
                wmma::mma_sync(acc[j], ah, bl, acc[j]);
                wmma::mma_sync(acc[j], al, bh, acc[j]);
            }
        }
        __syncthreads();
    }

#pragma unroll
    for (int j = 0; j < NPW; j++) {
        int nb = (ng * NPW + j) * 16;
        wmma::store_matrix_sync(outb + mt * 16 * OC + nb, acc[j], OC, wmma::mem_row_major);
    }
    __syncthreads();

    const int OQ = OC / 4;
    for (int k = tid; k < 64 * OQ; k += 256) {
        int m = k / OQ, oq = k - m * OQ;
        float4 v = *(float4*)(outb + m * OC + oq * 4);
        float4 bv = *(const float4*)(bias + oq * 4);
        v.x += bv.x; v.y += bv.y; v.z += bv.z; v.w += bv.w;
        if (RELU) {
            v.x = fmaxf(v.x, 0.f); v.y = fmaxf(v.y, 0.f);
            v.z = fmaxf(v.z, 0.f); v.w = fmaxf(v.w, 0.f);
        }
        int px = (r0 << 5) + m;
        *(float4*)(y + (size_t)px * OC + oq * 4) = v;
    }
}

// ---------------- channel-last conv, IC=1 ----------------
__global__ __launch_bounds__(128) void conv1_cl(const float* __restrict__ x,
                                                const float* __restrict__ wgt,
                                                const float* __restrict__ bias,
                                                float* __restrict__ y)
{
    __shared__ float xs[6 * 32];
    __shared__ float ws[4][9];
    __shared__ float bs[4];
    const int tid = threadIdx.x;
    const int obase = blockIdx.y * 4;
    x += blockIdx.z * HW;
    y += (size_t)blockIdx.z * DM * HW;
    const int r0 = blockIdx.x * 4;
    for (int k = tid; k < 6 * 32; k += 128) {
        int lr = k >> 5, c = k & 31;
        xs[k] = x[(((r0 - 1 + lr) & 31) << 5) + c];
    }
    if (tid < 36) ws[tid / 9][tid % 9] = wgt[(obase + tid / 9) * 9 + tid % 9];
    if (tid < 4)  bs[tid] = bias[obase + tid];
    __syncthreads();

    const int hl = tid >> 5, c = tid & 31;
    const int cm = (c + 31) & 31, cp = (c + 1) & 31;
    float xv[9];
#pragma unroll
    for (int tr = 0; tr < 3; tr++) {
        xv[tr * 3 + 0] = xs[(hl + tr) * 32 + cm];
        xv[tr * 3 + 1] = xs[(hl + tr) * 32 + c];
        xv[tr * 3 + 2] = xs[(hl + tr) * 32 + cp];
    }
    float4 o; float* op = &o.x;
#pragma unroll
    for (int j = 0; j < 4; j++) {
        float a = bs[j];
#pragma unroll
        for (int t9 = 0; t9 < 9; t9++) a = fmaf(xv[t9], ws[j][t9], a);
        op[j] = fmaxf(a, 0.f);
    }
    const int px = blockIdx.x * 128 + tid;
    *(float4*)&y[(size_t)px * DM + obase] = o;
}

// ---------------- channel-last conv, OC=1; 64 blocks ----------------
__global__ __launch_bounds__(128) void conv_out(const float* __restrict__ x,
                                                const float* __restrict__ wgt,
                                                const float* __restrict__ bias,
                                                float* __restrict__ y)
{
    __shared__ float4 xs[3 * 32 * 17];
    __shared__ float  ws[9][64];
    const int tid = threadIdx.x;
    const int r0 = blockIdx.x >> 1;
    const int chalf = blockIdx.x & 1;
    const float4* x4 = (const float4*)x;
    for (int k = tid; k < 3 * 32 * 16; k += 128) {
        int lr = k >> 9; int rem = k & 511; int c = rem >> 4; int icv = rem & 15;
        int row = (r0 - 1 + lr) & 31;
        xs[(lr * 32 + c) * 17 + icv] = x4[(((row << 5) + c) << 4) + icv];
    }
    for (int k = tid; k < 576; k += 128) {
        int tap = k >> 6, ic = k & 63;
        ws[tap][ic] = wgt[ic * 9 + tap];
    }
    __syncthreads();

    const int icg = tid & 7;
    const int c = chalf * 16 + (tid >> 3);
    const int cm = (c + 31) & 31, cp = (c + 1) & 31;
    float acc = 0.f;
#pragma unroll
    for (int tr = 0; tr < 3; tr++) {
#pragma unroll
        for (int tc = 0; tc < 3; tc++) {
            const int cx = (tc == 0) ? cm : ((tc == 1) ? c : cp);
            const float4* xp = &xs[(tr * 32 + cx) * 17];
            const float4* wp = (const float4*)&ws[tr * 3 + tc][0];
#pragma unroll
            for (int k = 0; k < 2; k++) {
                float4 xv = xp[icg * 2 + k];
                float4 wv = wp[icg * 2 + k];
                acc = fmaf(xv.x, wv.x, fmaf(xv.y, wv.y, fmaf(xv.z, wv.z, fmaf(xv.w, wv.w, acc))));
            }
        }
    }
    acc += __shfl_xor_sync(0xffffffffu, acc, 1);
    acc += __shfl_xor_sync(0xffffffffu, acc, 2);
    acc += __shfl_xor_sync(0xffffffffu, acc, 4);
    if (icg == 0) y[(r0 << 5) + c] = acc + bias[0];
}

__device__ __forceinline__ float sp_f(float x) { return (x > 20.f) ? x : log1pf(expf(x)); }

// ---------------- prep: e,f,(delta,u),B fields for encode slots ----------------
__global__ __launch_bounds__(128) void prep(const float* __restrict__ cc,
                                            const float* __restrict__ u,
                                            const float* __restrict__ dtp)
{
    const int s = blockIdx.z;
    cc += (size_t)s * HW * 96;
    u  += (size_t)s * HW * 64;
    const int tid = threadIdx.x;
    const int pl = tid >> 4, dq = tid & 15;
    const int p = blockIdx.x * 8 + pl;
    const float dti = dtp[0];

    float4 dc = *(const float4*)&cc[p * 96 + dq * 4];
    float4 dl4;
    dl4.x = sp_f(dc.x + dti); dl4.y = sp_f(dc.y + dti);
    dl4.z = sp_f(dc.z + dti); dl4.w = sp_f(dc.w + dti);
    float4 a4  = *(const float4*)&g_A[dq * 4];
    float4 ra4 = *(const float4*)&g_rA[dq * 4];
    float4 e4, f4;
    e4.x = __expf(dl4.x * a4.x); e4.y = __expf(dl4.y * a4.y);
    e4.z = __expf(dl4.z * a4.z); e4.w = __expf(dl4.w * a4.w);
    float4 u4 = *(const float4*)&u[p * 64 + dq * 4];
    f4.x = (e4.x - 1.f) * ra4.x * u4.x;
    f4.y = (e4.y - 1.f) * ra4.y * u4.y;
    f4.z = (e4.z - 1.f) * ra4.z * u4.z;
    f4.w = (e4.w - 1.f) * ra4.w * u4.w;

    float4* efp = (float4*)g_ef + (((size_t)s * HW + p) * 16 + dq) * 2;
    efp[0] = e4; efp[1] = f4;
    if (!g_uniA) {
        *(float4*)&g_dl[((size_t)s * HW + p) * 64 + dq * 4] = dl4;
        *(float4*)&g_uf[((size_t)s * HW + p) * 64 + dq * 4] = u4;
    }
    g_Bf[((size_t)s * HW + p) * 16 + dq] = cc[p * 96 + 64 + dq];
}

// ---- per-chunk v evaluation helper (uniA fast path) ----
template<int CNT>
__device__ __forceinline__ void yv_chunk(int vbase, int S, int h, int w, int dq,
                                         const float* GsRow, float g0,
                                         float4 e4o, float4 f4o, float4& best)
{
    float4 P[CNT], acc[CNT];
#pragma unroll
    for (int j = 0; j < CNT; j++) {
        acc[j].x = f4o.x * g0; acc[j].y = f4o.y * g0;
        acc[j].z = f4o.z * g0; acc[j].w = f4o.w * g0;
        P[j] = e4o;
    }
#pragma unroll 1
    for (int k = 1; k < S; k++) {
#pragma unroll
        for (int j = 0; j < CNT; j++) {
            int v = vbase + j;
            int vx = v / 5 - 2, vy = v % 5 - 2;
            int hh = (h + k * vy) & 31;
            int ww = (w + k * vx) & 31;
            int x = (hh << 5) + ww;
            const float4* ep = (const float4*)g_ef + (((size_t)(S - 1 - k) * HW + x) * 16 + dq) * 2;
            float4 ee = ep[0];
            float4 ff = ep[1];
            float Gv = GsRow[v * MAXS + k];
            acc[j].x = fmaf(P[j].x * ff.x, Gv, acc[j].x);
            acc[j].y = fmaf(P[j].y * ff.y, Gv, acc[j].y);
            acc[j].z = fmaf(P[j].z * ff.z, Gv, acc[j].z);
            acc[j].w = fmaf(P[j].w * ff.w, Gv, acc[j].w);
            P[j].x *= ee.x; P[j].y *= ee.y; P[j].z *= ee.z; P[j].w *= ee.w;
        }
    }
#pragma unroll
    for (int j = 0; j < CNT; j++) {
        best.x = fmaxf(best.x, acc[j].x);
        best.y = fmaxf(best.y, acc[j].y);
        best.z = fmaxf(best.z, acc[j].z);
        best.w = fmaxf(best.w, acc[j].w);
    }
}

// ---------------- fused y-kernel (decode step S); 128 thr, v-split x2 ----------------
__global__ __launch_bounds__(128) void fused_y(const float* __restrict__ cc,
                                               const float* __restrict__ u,
                                               const float* __restrict__ Dskip,
                                               const float* __restrict__ dtp,
                                               int S, float* __restrict__ ymax)
{
    __shared__ float Bs[4][16], Cs[4][16];
    __shared__ float Gs[4][NV][MAXS];
    __shared__ float G0[4];
    __shared__ float4 sb1[4][16];
    const int tid = threadIdx.x;
    const int hf = tid >> 6;
    const int t64 = tid & 63;
    const int pl = t64 >> 4, dq = t64 & 15;
    const int p0 = blockIdx.x * 4;
    const int p = p0 + pl;
    const int h = p >> 5, w = p & 31;
    const int slotS = S - 1;
    const float dti = dtp[0];

    float4 dc = *(const float4*)&cc[p * 96 + dq * 4];
    float4 dl4;
    dl4.x = sp_f(dc.x + dti); dl4.y = sp_f(dc.y + dti);
    dl4.z = sp_f(dc.z + dti); dl4.w = sp_f(dc.w + dti);
    float4 a4  = *(const float4*)&g_A[dq * 4];
    float4 ra4 = *(const float4*)&g_rA[dq * 4];
    float4 e4o, f4o;
    e4o.x = __expf(dl4.x * a4.x); e4o.y = __expf(dl4.y * a4.y);
    e4o.z = __expf(dl4.z * a4.z); e4o.w = __expf(dl4.w * a4.w);
    float4 u4 = *(const float4*)&u[p * 64 + dq * 4];
    f4o.x = (e4o.x - 1.f) * ra4.x * u4.x;
    f4o.y = (e4o.y - 1.f) * ra4.y * u4.y;
    f4o.z = (e4o.z - 1.f) * ra4.z * u4.z;
    f4o.w = (e4o.w - 1.f) * ra4.w * u4.w;

    if (hf == 0) {
        float4* efp = (float4*)g_ef + (((size_t)slotS * HW + p) * 16 + dq) * 2;
        efp[0] = e4o; efp[1] = f4o;
        if (!g_uniA) {
            *(float4*)&g_dl[((size_t)slotS * HW + p) * 64 + dq * 4] = dl4;
            *(float4*)&g_uf[((size_t)slotS * HW + p) * 64 + dq * 4] = u4;
        }
        float bv = cc[p * 96 + 64 + dq];
        g_Bf[((size_t)slotS * HW + p) * 16 + dq] = bv;
        Bs[pl][dq] = bv;
        Cs[pl][dq] = cc[p * 96 + 80 + dq];
    }
    __syncthreads();

    if (tid < 4) {
        float s = 0.f;
#pragma unroll
        for (int n = 0; n < 16; n++) s += Bs[tid][n] * Cs[tid][n];
        G0[tid] = s;
    }
    const int Sm1 = S - 1;
    const int tot = 4 * NV * Sm1;
    for (int idx = tid; idx < tot; idx += 128) {
        int i = idx / (NV * Sm1);
        int rem = idx - i * (NV * Sm1);
        int v = rem / Sm1;
        int k = rem - v * Sm1 + 1;
        int vx = v / 5 - 2, vy = v % 5 - 2;
        int pp = p0 + i;
        int hh = ((pp >> 5) + k * vy) & 31;
        int ww = ((pp & 31) + k * vx) & 31;
        int x = (hh << 5) + ww;
        const float* bp = &g_Bf[((size_t)(S - 1 - k) * HW + x) * 16];
        float s = 0.f;
#pragma unroll
        for (int n = 0; n < 16; n++) s += bp[n] * Cs[i][n];
        Gs[i][v][k] = s;
    }
    __syncthreads();

    float4 best = {-3e38f, -3e38f, -3e38f, -3e38f};
    if (g_uniA) {
        const float g0 = G0[pl];
        const float* GsRow = &Gs[pl][0][0];
        if (hf == 0) {
            yv_chunk<4>(0, S, h, w, dq, GsRow, g0, e4o, f4o, best);
            yv_chunk<4>(4, S, h, w, dq, GsRow, g0, e4o, f4o, best);
            yv_chunk<4>(8, S, h, w, dq, GsRow, g0, e4o, f4o, best);
        } else {
            yv_chunk<4>(12, S, h, w, dq, GsRow, g0, e4o, f4o, best);
            yv_chunk<4>(16, S, h, w, dq, GsRow, g0, e4o, f4o, best);
            yv_chunk<5>(20, S, h, w, dq, GsRow, g0, e4o, f4o, best);
        }
    } else if (hf == 0) {
        // generic A fallback (correct for any A)
#pragma unroll 1
        for (int v = 0; v < NV; v++) {
            int vx = v / 5 - 2, vy = v % 5 - 2;
            float4 accv = {0.f, 0.f, 0.f, 0.f};
#pragma unroll 1
            for (int n = 0; n < 16; n++) {
                float4 an4 = *(const float4*)&g_A[n * 64 + dq * 4];
                float4 rn4 = *(const float4*)&g_rA[n * 64 + dq * 4];
                float C = Cs[pl][n];
                float4 e0;
                e0.x = __expf(dl4.x * an4.x); e0.y = __expf(dl4.y * an4.y);
                e0.z = __expf(dl4.z * an4.z); e0.w = __expf(dl4.w * an4.w);
                float bc = Bs[pl][n] * C;
                float4 P = e0, a4c;
                a4c.x = (e0.x - 1.f) * rn4.x * u4.x * bc;
                a4c.y = (e0.y - 1.f) * rn4.y * u4.y * bc;
                a4c.z = (e0.z - 1.f) * rn4.z * u4.z * bc;
                a4c.w = (e0.w - 1.f) * rn4.w * u4.w * bc;
                for (int k = 1; k < S; k++) {
                    int hh = (h + k * vy) & 31;
                    int ww = (w + k * vx) & 31;
                    int x = (hh << 5) + ww;
                    int sl = S - 1 - k;
                    float4 dl = *(const float4*)&g_dl[((size_t)sl * HW + x) * 64 + dq * 4];
                    float4 uu = *(const float4*)&g_uf[((size_t)sl * HW + x) * 64 + dq * 4];
                    float Bt = g_Bf[((size_t)sl * HW + x) * 16 + n] * C;
                    float4 ee;
                    ee.x = __expf(dl.x * an4.x); ee.y = __expf(dl.y * an4.y);
                    ee.z = __expf(dl.z * an4.z); ee.w = __expf(dl.w * an4.w);
                    a4c.x = fmaf(P.x * (ee.x - 1.f) * rn4.x * uu.x, Bt, a4c.x);
                    a4c.y = fmaf(P.y * (ee.y - 1.f) * rn4.y * uu.y, Bt, a4c.y);
                    a4c.z = fmaf(P.z * (ee.z - 1.f) * rn4.z * uu.z, Bt, a4c.z);
                    a4c.w = fmaf(P.w * (ee.w - 1.f) * rn4.w * uu.w, Bt, a4c.w);
                    P.x *= ee.x; P.y *= ee.y; P.z *= ee.z; P.w *= ee.w;
                }
                accv.x += a4c.x; accv.y += a4c.y; accv.z += a4c.z; accv.w += a4c.w;
            }
            best.x = fmaxf(best.x, accv.x);
            best.y = fmaxf(best.y, accv.y);
            best.z = fmaxf(best.z, accv.z);
            best.w = fmaxf(best.w, accv.w);
        }
    }

    if (hf == 1) sb1[pl][dq] = best;
    __syncthreads();
    if (hf == 0) {
        float4 b1 = sb1[pl][dq];
        best.x = fmaxf(best.x, b1.x);
        best.y = fmaxf(best.y, b1.y);
        best.z = fmaxf(best.z, b1.z);
        best.w = fmaxf(best.w, b1.w);
        float4 dk = *(const float4*)&Dskip[dq * 4];
        float4 o;
        o.x = fmaf(dk.x, u4.x, best.x);
        o.y = fmaf(dk.y, u4.y, best.y);
        o.z = fmaf(dk.z, u4.z, best.z);
        o.w = fmaf(dk.w, u4.w, best.w);
        *(float4*)&ymax[p * 64 + dq * 4] = o;
    }
}

// ---------------- launch ----------------
extern "C" void kernel_launch(void* const* d_in, const int* in_sizes, int n_in,
                              void* d_out, int out_size)
{
    const float* input_seq = (const float*)d_in[0];
    const float* enc_w1 = (const float*)d_in[1];
    const float* enc_b1 = (const float*)d_in[2];
    const float* enc_w2 = (const float*)d_in[3];
    const float* enc_b2 = (const float*)d_in[4];
    const float* wd     = (const float*)d_in[5];
    const float* bd     = (const float*)d_in[6];
    const float* wB     = (const float*)d_in[7];
    const float* wC     = (const float*)d_in[8];
    const float* logA   = (const float*)d_in[9];
    const float* Dskip  = (const float*)d_in[10];
    const float* dt_inv = (const float*)d_in[11];
    const float* dec_w1 = (const float*)d_in[12];
    const float* dec_b1 = (const float*)d_in[13];
    const float* dec_w2 = (const float*)d_in[14];
    const float* dec_b2 = (const float*)d_in[15];
    const float* dec_w3 = (const float*)d_in[16];
    const float* dec_b3 = (const float*)d_in[17];
    float* out = (float*)d_out;

    float *p_u, *p_e1, *p_cc, *p_bpack, *p_ymax, *p_d1, *p_d2;
    __nv_bfloat16 *p_wfH, *p_wfL;
    cudaGetSymbolAddress((void**)&p_u, g_u);
    cudaGetSymbolAddress((void**)&p_e1, g_e1);
    cudaGetSymbolAddress((void**)&p_cc, g_cc);
    cudaGetSymbolAddress((void**)&p_bpack, g_bpack);
    cudaGetSymbolAddress((void**)&p_ymax, g_ymax);
    cudaGetSymbolAddress((void**)&p_d1, g_d1);
    cudaGetSymbolAddress((void**)&p_d2, g_d2);
    cudaGetSymbolAddress((void**)&p_wfH, g_wfH);
    cudaGetSymbolAddress((void**)&p_wfL, g_wfL);

    cudaFuncSetAttribute(conv_wmma<64, true>,  cudaFuncAttributeMaxDynamicSharedMemorySize, SMW);
    cudaFuncSetAttribute(conv_wmma<96, false>, cudaFuncAttributeMaxDynamicSharedMemorySize, SMW);

    pack_all<<<648, 256>>>(wd, bd, wB, wC, logA, enc_w2, dec_w1, dec_w2);
    check_uni<<<1, 256>>>(logA);

    // ---- encode: batched over 4 frames ----
    conv1_cl<<<dim3(8, 16, TIN), 128>>>(input_seq, enc_w1, enc_b1, p_e1);
    conv_wmma<64, true><<<dim3(16, 1, TIN), 256, SMW>>>(p_e1, p_wfH + WOFF_E, p_wfL + WOFF_E, enc_b2, p_u);
    conv_wmma<96, false><<<dim3(16, 1, TIN), 256, SMW>>>(p_u, p_wfH + WOFF_C, p_wfL + WOFF_C, p_bpack, p_cc);
    prep<<<dim3(128, 1, TIN), 128>>>(p_cc, p_u, dt_inv);

    // ---- decode ----
    int steps = out_size / HW;
    for (int t = 0; t < steps; t++) {
        const float* src = (t == 0) ? (input_seq + 3 * HW) : (out + (size_t)(t - 1) * HW);
        conv1_cl<<<dim3(8, 16, 1), 128>>>(src, enc_w1, enc_b1, p_e1);
        conv_wmma<64, true><<<dim3(16, 1, 1), 256, SMW>>>(p_e1, p_wfH + WOFF_E, p_wfL + WOFF_E, enc_b2, p_u);
        conv_wmma<96, false><<<dim3(16, 1, 1), 256, SMW>>>(p_u, p_wfH + WOFF_C, p_wfL + WOFF_C, p_bpack, p_cc);
        fused_y<<<256, 128>>>(p_cc, p_u, Dskip, dt_inv, TIN + 1 + t, p_ymax);
        conv_wmma<64, true><<<dim3(16, 1, 1), 256, SMW>>>(p_ymax, p_wfH + WOFF_D1, p_wfL + WOFF_D1, dec_b1, p_d1);
        conv_wmma<64, true><<<dim3(16, 1, 1), 256, SMW>>>(p_d1, p_wfH + WOFF_D2, p_wfL + WOFF_D2, dec_b2, p_d2);
        conv_out<<<64, 128>>>(p_d2, dec_w3, dec_b3, out + (size_t)t * HW);
    }
}

// round 17
// speedup vs baseline: 3.1414x; 3.1414x over previous
#include <cuda_runtime.h>
#include <math.h>

#define HW   1024
#define DM   64
#define DS   16
#define NV   25
#define TIN  4
#define MAXS 8

// packed fp32x2 FMA (sm_100+; only reachable via PTX)
#define FMA2(d, a, b) asm("fma.rn.f32x2 %0, %1, %2, %0;" : "+l"(d) : "l"(a), "l"(b))
#define UNPK2(lo, hi, v) asm("mov.b64 {%0, %1}, %2;" : "=f"(lo), "=f"(hi) : "l"(v))

// ---------------- scratch (static device globals; no allocation) ----------------
__device__ __align__(128) float g_u[TIN * HW * DM];
__device__ __align__(128) float g_e1[TIN * HW * DM];
__device__ __align__(128) float g_cc[TIN * HW * 96];            // [t][px][dconv|B|C]
__device__ __align__(128) float g_wt96[96 * 576];               // wd|wB|wC transposed [oc][tap][ic]
__device__ __align__(128) float g_wtE[64 * 576];
__device__ __align__(128) float g_wtD1[64 * 576];
__device__ __align__(128) float g_wtD2[64 * 576];
__device__ __align__(128) float g_bpack[96];
__device__ __align__(128) float g_A[DS * DM];
__device__ __align__(128) float g_rA[DS * DM];
__device__ int   g_uniA;
__device__ __align__(128) float g_ef[MAXS * HW * DM * 2];
__device__ __align__(128) float g_dl[MAXS * HW * DM];
__device__ __align__(128) float g_uf[MAXS * HW * DM];
__device__ __align__(128) float g_Bf[MAXS * HW * DS];
__device__ __align__(128) float g_ymax[HW * DM];
__device__ __align__(128) float g_d1[HW * DM];
__device__ __align__(128) float g_d2[HW * DM];

// ---------------- pack: transposed weights + bias + A fields ----------------
__global__ void pack_all(const float* __restrict__ wd, const float* __restrict__ bd,
                         const float* __restrict__ wB, const float* __restrict__ wC,
                         const float* __restrict__ logA,
                         const float* __restrict__ ew2, const float* __restrict__ dw1,
                         const float* __restrict__ dw2)
{
    int k = blockIdx.x * 256 + threadIdx.x;
    const int R0 = 96 * 576;
    const int R1 = R0 + 3 * 64 * 576;
    if (k < R0) {
        int oc = k / 576, rem = k - oc * 576;
        int tap = rem >> 6, ic = rem & 63;
        float v;
        if (oc < 64)      v = wd[oc * 576 + ic * 9 + tap];
        else if (oc < 80) v = wB[(oc - 64) * 576 + ic * 9 + tap];
        else              v = wC[(oc - 80) * 576 + ic * 9 + tap];
        g_wt96[k] = v;
    } else if (k < R1) {
        int k2 = k - R0;
        int which = k2 / (64 * 576);
        int k3 = k2 - which * (64 * 576);
        int oc = k3 / 576, rem = k3 - oc * 576;
        int tap = rem >> 6, ic = rem & 63;
        const float* s = (which == 0) ? ew2 : ((which == 1) ? dw1 : dw2);
        float v = s[oc * 576 + ic * 9 + tap];
        if (which == 0) g_wtE[k3] = v;
        else if (which == 1) g_wtD1[k3] = v;
        else g_wtD2[k3] = v;
    }
    if (k < DM)       g_bpack[k] = bd[k];
    else if (k < 96)  g_bpack[k] = 0.f;
    if (k < DS * DM) {
        int n = k >> 6, d = k & 63;
        float a = -expf(logA[d * DS + n]);
        g_A[k] = a;
        g_rA[k] = 1.f / a;
    }
}

__global__ void check_uni(const float* __restrict__ logA)
{
    __shared__ int ok;
    if (threadIdx.x == 0) ok = 1;
    __syncthreads();
    bool bad = false;
    for (int i = threadIdx.x; i < DM * DS; i += 256)
        if (logA[i] != logA[(i / DS) * DS]) bad = true;
    if (bad) atomicAnd(&ok, 0);
    __syncthreads();
    if (threadIdx.x == 0) g_uniA = ok;
}

// ---------------- f32x2 conv, 4 rows x 8 oc per block, 256 thr (batched path) -------
template <bool RELU>
__global__ __launch_bounds__(256) void conv_f4w(const float* __restrict__ x,
                                                const float* __restrict__ wgt,
                                                const float* __restrict__ bias,
                                                float* __restrict__ y, int OC)
{
    extern __shared__ float4 xs[];         // 51 KB
    __shared__ float  ws[8][9][64];
    __shared__ float  bs[8];
    __shared__ float4 red[4][32][2];
    const int tid = threadIdx.x;
    const int obase = blockIdx.y * 8;
    const int r0 = blockIdx.x * 4;
    x += (size_t)blockIdx.z * DM * HW;
    y += (size_t)blockIdx.z * (size_t)OC * HW;

    const float4* x4 = (const float4*)x;
    for (int k = tid; k < 6 * 32 * 16; k += 256) {
        int lr = k >> 9; int rem = k & 511; int c = rem >> 4; int icv = rem & 15;
        int row = (r0 - 1 + lr) & 31;
        xs[(lr * 32 + c) * 17 + icv] = x4[(((row << 5) + c) << 4) + icv];
    }
    {
        const float4* wsrc = (const float4*)(wgt + (size_t)obase * 576);
        float4* wdst = (float4*)&ws[0][0][0];
        for (int k = tid; k < 1152; k += 256) wdst[k] = wsrc[k];
    }
    if (tid < 8) bs[tid] = bias[obase + tid];
    __syncthreads();

    const int half = tid >> 7;
    const int ocp  = (tid >> 5) & 3;
    const int c    = tid & 31;
    const int cm = (c + 31) & 31, cp = (c + 1) & 31;
    const int hb = half * 8;

    unsigned long long acc[4][2];
#pragma unroll
    for (int p = 0; p < 4; p++) { acc[p][0] = 0ull; acc[p][1] = 0ull; }

#pragma unroll
    for (int tc = 0; tc < 3; tc++) {
        const int cx = (tc == 0) ? cm : ((tc == 1) ? c : cp);
        const ulonglong2* xr[6];
#pragma unroll
        for (int r = 0; r < 6; r++) xr[r] = (const ulonglong2*)&xs[(r * 32 + cx) * 17 + hb];
        const ulonglong2* w0t[3];
        const ulonglong2* w1t[3];
#pragma unroll
        for (int tr = 0; tr < 3; tr++) {
            w0t[tr] = (const ulonglong2*)&ws[ocp * 2 + 0][tr * 3 + tc][half * 32];
            w1t[tr] = (const ulonglong2*)&ws[ocp * 2 + 1][tr * 3 + tc][half * 32];
        }
#pragma unroll
        for (int icv = 0; icv < 8; icv++) {
            ulonglong2 xv[6];
#pragma unroll
            for (int r = 0; r < 6; r++) xv[r] = xr[r][icv];
#pragma unroll
            for (int tr = 0; tr < 3; tr++) {
                ulonglong2 wa = w0t[tr][icv];
                ulonglong2 wb = w1t[tr][icv];
#pragma unroll
                for (int p = 0; p < 4; p++) {
                    FMA2(acc[p][0], xv[p + tr].x, wa.x); FMA2(acc[p][0], xv[p + tr].y, wa.y);
                    FMA2(acc[p][1], xv[p + tr].x, wb.x); FMA2(acc[p][1], xv[p + tr].y, wb.y);
                }
            }
        }
    }

    float s[4][2];
#pragma unroll
    for (int p = 0; p < 4; p++) {
        float lo, hi;
        UNPK2(lo, hi, acc[p][0]); s[p][0] = lo + hi;
        UNPK2(lo, hi, acc[p][1]); s[p][1] = lo + hi;
    }

    if (half) {
        float4 rA; rA.x = s[0][0]; rA.y = s[0][1]; rA.z = s[1][0]; rA.w = s[1][1];
        float4 rB; rB.x = s[2][0]; rB.y = s[2][1]; rB.z = s[3][0]; rB.w = s[3][1];
        red[ocp][c][0] = rA; red[ocp][c][1] = rB;
    }
    __syncthreads();
    if (!half) {
        float4 rA = red[ocp][c][0];
        float4 rB = red[ocp][c][1];
        float b0 = bs[ocp * 2], b1 = bs[ocp * 2 + 1];
        float o[4][2];
        o[0][0] = s[0][0] + rA.x + b0; o[0][1] = s[0][1] + rA.y + b1;
        o[1][0] = s[1][0] + rA.z + b0; o[1][1] = s[1][1] + rA.w + b1;
        o[2][0] = s[2][0] + rB.x + b0; o[2][1] = s[2][1] + rB.y + b1;
        o[3][0] = s[3][0] + rB.z + b0; o[3][1] = s[3][1] + rB.w + b1;
#pragma unroll
        for (int p = 0; p < 4; p++) {
            float v0 = o[p][0], v1 = o[p][1];
            if (RELU) { v0 = fmaxf(v0, 0.f); v1 = fmaxf(v1, 0.f); }
            const int px = ((r0 + p) << 5) + c;
            float2 ov; ov.x = v0; ov.y = v1;
            *(float2*)&y[(size_t)px * OC + obase + ocp * 2] = ov;
        }
    }
}

// ---------------- f32x2 conv, 4 rows, ic-quartered, 256 thr (single-frame path) -----
// tid = c(32) x ocp(2) x quarter(4). Per-thread work halved vs f4 -> 2 warps/SMSP.
template <bool RELU>
__global__ __launch_bounds__(256) void conv_f4q(const float* __restrict__ x,
                                                const float* __restrict__ wgt,
                                                const float* __restrict__ bias,
                                                float* __restrict__ y, int OC)
{
    extern __shared__ float4 xs[];         // 51 KB dynamic
    __shared__ float  ws[4][9][64];        // 9 KB
    __shared__ float  bs[4];
    __shared__ float4 red[3][2][32][2];    // 12 KB
    const int tid = threadIdx.x;
    const int obase = blockIdx.y * 4;
    const int r0 = blockIdx.x * 4;
    x += (size_t)blockIdx.z * DM * HW;
    y += (size_t)blockIdx.z * (size_t)OC * HW;

    const float4* x4 = (const float4*)x;
    for (int k = tid; k < 6 * 32 * 16; k += 256) {
        int lr = k >> 9; int rem = k & 511; int c = rem >> 4; int icv = rem & 15;
        int row = (r0 - 1 + lr) & 31;
        xs[(lr * 32 + c) * 17 + icv] = x4[(((row << 5) + c) << 4) + icv];
    }
    {
        const float4* wsrc = (const float4*)(wgt + (size_t)obase * 576);
        float4* wdst = (float4*)&ws[0][0][0];
        for (int k = tid; k < 576; k += 256) wdst[k] = wsrc[k];
    }
    if (tid < 4) bs[tid] = bias[obase + tid];
    __syncthreads();

    const int q   = tid >> 6;              // ic-quarter 0..3
    const int ocp = (tid >> 5) & 1;
    const int c   = tid & 31;
    const int cm = (c + 31) & 31, cp = (c + 1) & 31;
    const int hb = q * 4;                  // float4 offset into ic

    unsigned long long acc[4][2];
#pragma unroll
    for (int p = 0; p < 4; p++) { acc[p][0] = 0ull; acc[p][1] = 0ull; }

#pragma unroll
    for (int tc = 0; tc < 3; tc++) {
        const int cx = (tc == 0) ? cm : ((tc == 1) ? c : cp);
        const ulonglong2* xr[6];
#pragma unroll
        for (int r = 0; r < 6; r++) xr[r] = (const ulonglong2*)&xs[(r * 32 + cx) * 17 + hb];
        const ulonglong2* w0t[3];
        const ulonglong2* w1t[3];
#pragma unroll
        for (int tr = 0; tr < 3; tr++) {
            w0t[tr] = (const ulonglong2*)&ws[ocp * 2 + 0][tr * 3 + tc][q * 16];
            w1t[tr] = (const ulonglong2*)&ws[ocp * 2 + 1][tr * 3 + tc][q * 16];
        }
#pragma unroll
        for (int icv = 0; icv < 4; icv++) {
            ulonglong2 xv[6];
#pragma unroll
            for (int r = 0; r < 6; r++) xv[r] = xr[r][icv];
#pragma unroll
            for (int tr = 0; tr < 3; tr++) {
                ulonglong2 wa = w0t[tr][icv];
                ulonglong2 wb = w1t[tr][icv];
#pragma unroll
                for (int p = 0; p < 4; p++) {
                    FMA2(acc[p][0], xv[p + tr].x, wa.x); FMA2(acc[p][0], xv[p + tr].y, wa.y);
                    FMA2(acc[p][1], xv[p + tr].x, wb.x); FMA2(acc[p][1], xv[p + tr].y, wb.y);
                }
            }
        }
    }

    float s[4][2];
#pragma unroll
    for (int p = 0; p < 4; p++) {
        float lo, hi;
        UNPK2(lo, hi, acc[p][0]); s[p][0] = lo + hi;
        UNPK2(lo, hi, acc[p][1]); s[p][1] = lo + hi;
    }

    if (q) {
        float4 rA; rA.x = s[0][0]; rA.y = s[0][1]; rA.z = s[1][0]; rA.w = s[1][1];
        float4 rB; rB.x = s[2][0]; rB.y = s[2][1]; rB.z = s[3][0]; rB.w = s[3][1];
        red[q - 1][ocp][c][0] = rA; red[q - 1][ocp][c][1] = rB;
    }
    __syncthreads();
    if (q == 0) {
        float4 rA1 = red[0][ocp][c][0], rB1 = red[0][ocp][c][1];
        float4 rA2 = red[1][ocp][c][0], rB2 = red[1][ocp][c][1];
        float4 rA3 = red[2][ocp][c][0], rB3 = red[2][ocp][c][1];
        float b0 = bs[ocp * 2], b1 = bs[ocp * 2 + 1];
        float o[4][2];
        o[0][0] = s[0][0] + rA1.x + rA2.x + rA3.x + b0;
        o[0][1] = s[0][1] + rA1.y + rA2.y + rA3.y + b1;
        o[1][0] = s[1][0] + rA1.z + rA2.z + rA3.z + b0;
        o[1][1] = s[1][1] + rA1.w + rA2.w + rA3.w + b1;
        o[2][0] = s[2][0] + rB1.x + rB2.x + rB3.x + b0;
        o[2][1] = s[2][1] + rB1.y + rB2.y + rB3.y + b1;
        o[3][0] = s[3][0] + rB1.z + rB2.z + rB3.z + b0;
        o[3][1] = s[3][1] + rB1.w + rB2.w + rB3.w + b1;
#pragma unroll
        for (int p = 0; p < 4; p++) {
            float v0 = o[p][0], v1 = o[p][1];
            if (RELU) { v0 = fmaxf(v0, 0.f); v1 = fmaxf(v1, 0.f); }
            const int px = ((r0 + p) << 5) + c;
            float2 ov; ov.x = v0; ov.y = v1;
            *(float2*)&y[(size_t)px * OC + obase + ocp * 2] = ov;
        }
    }
}

// ---------------- channel-last conv, IC=1 ----------------
__global__ __launch_bounds__(128) void conv1_cl(const float* __restrict__ x,
                                                const float* __restrict__ wgt,
                                                const float* __restrict__ bias,
                                                float* __restrict__ y)
{
    __shared__ float xs[6 * 32];
    __shared__ float ws[4][9];
    __shared__ float bs[4];
    const int tid = threadIdx.x;
    const int obase = blockIdx.y * 4;
    x += blockIdx.z * HW;
    y += (size_t)blockIdx.z * DM * HW;
    const int r0 = blockIdx.x * 4;
    for (int k = tid; k < 6 * 32; k += 128) {
        int lr = k >> 5, c = k & 31;
        xs[k] = x[(((r0 - 1 + lr) & 31) << 5) + c];
    }
    if (tid < 36) ws[tid / 9][tid % 9] = wgt[(obase + tid / 9) * 9 + tid % 9];
    if (tid < 4)  bs[tid] = bias[obase + tid];
    __syncthreads();

    const int hl = tid >> 5, c = tid & 31;
    const int cm = (c + 31) & 31, cp = (c + 1) & 31;
    float xv[9];
#pragma unroll
    for (int tr = 0; tr < 3; tr++) {
        xv[tr * 3 + 0] = xs[(hl + tr) * 32 + cm];
        xv[tr * 3 + 1] = xs[(hl + tr) * 32 + c];
        xv[tr * 3 + 2] = xs[(hl + tr) * 32 + cp];
    }
    float4 o; float* op = &o.x;
#pragma unroll
    for (int j = 0; j < 4; j++) {
        float a = bs[j];
#pragma unroll
        for (int t9 = 0; t9 < 9; t9++) a = fmaf(xv[t9], ws[j][t9], a);
        op[j] = fmaxf(a, 0.f);
    }
    const int px = blockIdx.x * 128 + tid;
    *(float4*)&y[(size_t)px * DM + obase] = o;
}

// ---------------- channel-last conv, OC=1; 64 blocks ----------------
__global__ __launch_bounds__(128) void conv_out(const float* __restrict__ x,
                                                const float* __restrict__ wgt,
                                                const float* __restrict__ bias,
                                                float* __restrict__ y)
{
    __shared__ float4 xs[3 * 32 * 17];
    __shared__ float  ws[9][64];
    const int tid = threadIdx.x;
    const int r0 = blockIdx.x >> 1;
    const int chalf = blockIdx.x & 1;
    const float4* x4 = (const float4*)x;
    for (int k = tid; k < 3 * 32 * 16; k += 128) {
        int lr = k >> 9; int rem = k & 511; int c = rem >> 4; int icv = rem & 15;
        int row = (r0 - 1 + lr) & 31;
        xs[(lr * 32 + c) * 17 + icv] = x4[(((row << 5) + c) << 4) + icv];
    }
    for (int k = tid; k < 576; k += 128) {
        int tap = k >> 6, ic = k & 63;
        ws[tap][ic] = wgt[ic * 9 + tap];
    }
    __syncthreads();

    const int icg = tid & 7;
    const int c = chalf * 16 + (tid >> 3);
    const int cm = (c + 31) & 31, cp = (c + 1) & 31;
    float acc = 0.f;
#pragma unroll
    for (int tr = 0; tr < 3; tr++) {
#pragma unroll
        for (int tc = 0; tc < 3; tc++) {
            const int cx = (tc == 0) ? cm : ((tc == 1) ? c : cp);
            const float4* xp = &xs[(tr * 32 + cx) * 17];
            const float4* wp = (const float4*)&ws[tr * 3 + tc][0];
#pragma unroll
            for (int k = 0; k < 2; k++) {
                float4 xv = xp[icg * 2 + k];
                float4 wv = wp[icg * 2 + k];
                acc = fmaf(xv.x, wv.x, fmaf(xv.y, wv.y, fmaf(xv.z, wv.z, fmaf(xv.w, wv.w, acc))));
            }
        }
    }
    acc += __shfl_xor_sync(0xffffffffu, acc, 1);
    acc += __shfl_xor_sync(0xffffffffu, acc, 2);
    acc += __shfl_xor_sync(0xffffffffu, acc, 4);
    if (icg == 0) y[(r0 << 5) + c] = acc + bias[0];
}

__device__ __forceinline__ float sp_f(float x) { return (x > 20.f) ? x : log1pf(expf(x)); }

// ---------------- prep: e,f,(delta,u),B fields for encode slots ----------------
__global__ __launch_bounds__(128) void prep(const float* __restrict__ cc,
                                            const float* __restrict__ u,
                                            const float* __restrict__ dtp)
{
    const int s = blockIdx.z;
    cc += (size_t)s * HW * 96;
    u  += (size_t)s * HW * 64;
    const int tid = threadIdx.x;
    const int pl = tid >> 4, dq = tid & 15;
    const int p = blockIdx.x * 8 + pl;
    const float dti = dtp[0];

    float4 dc = *(const float4*)&cc[p * 96 + dq * 4];
    float4 dl4;
    dl4.x = sp_f(dc.x + dti); dl4.y = sp_f(dc.y + dti);
    dl4.z = sp_f(dc.z + dti); dl4.w = sp_f(dc.w + dti);
    float4 a4  = *(const float4*)&g_A[dq * 4];
    float4 ra4 = *(const float4*)&g_rA[dq * 4];
    float4 e4, f4;
    e4.x = __expf(dl4.x * a4.x); e4.y = __expf(dl4.y * a4.y);
    e4.z = __expf(dl4.z * a4.z); e4.w = __expf(dl4.w * a4.w);
    float4 u4 = *(const float4*)&u[p * 64 + dq * 4];
    f4.x = (e4.x - 1.f) * ra4.x * u4.x;
    f4.y = (e4.y - 1.f) * ra4.y * u4.y;
    f4.z = (e4.z - 1.f) * ra4.z * u4.z;
    f4.w = (e4.w - 1.f) * ra4.w * u4.w;

    float4* efp = (float4*)g_ef + (((size_t)s * HW + p) * 16 + dq) * 2;
    efp[0] = e4; efp[1] = f4;
    if (!g_uniA) {
        *(float4*)&g_dl[((size_t)s * HW + p) * 64 + dq * 4] = dl4;
        *(float4*)&g_uf[((size_t)s * HW + p) * 64 + dq * 4] = u4;
    }
    g_Bf[((size_t)s * HW + p) * 16 + dq] = cc[p * 96 + 64 + dq];
}

// ---- per-chunk v evaluation helper (uniA fast path) ----
template<int CNT>
__device__ __forceinline__ void yv_chunk(int vbase, int S, int h, int w, int dq,
                                         const float* GsRow, float g0,
                                         float4 e4o, float4 f4o, float4& best)
{
    float4 P[CNT], acc[CNT];
#pragma unroll
    for (int j = 0; j < CNT; j++) {
        acc[j].x = f4o.x * g0; acc[j].y = f4o.y * g0;
        acc[j].z = f4o.z * g0; acc[j].w = f4o.w * g0;
        P[j] = e4o;
    }
#pragma unroll 1
    for (int k = 1; k < S; k++) {
#pragma unroll
        for (int j = 0; j < CNT; j++) {
            int v = vbase + j;
            int vx = v / 5 - 2, vy = v % 5 - 2;
            int hh = (h + k * vy) & 31;
            int ww = (w + k * vx) & 31;
            int x = (hh << 5) + ww;
            const float4* ep = (const float4*)g_ef + (((size_t)(S - 1 - k) * HW + x) * 16 + dq) * 2;
            float4 ee = ep[0];
            float4 ff = ep[1];
            float Gv = GsRow[v * MAXS + k];
            acc[j].x = fmaf(P[j].x * ff.x, Gv, acc[j].x);
            acc[j].y = fmaf(P[j].y * ff.y, Gv, acc[j].y);
            acc[j].z = fmaf(P[j].z * ff.z, Gv, acc[j].z);
            acc[j].w = fmaf(P[j].w * ff.w, Gv, acc[j].w);
            P[j].x *= ee.x; P[j].y *= ee.y; P[j].z *= ee.z; P[j].w *= ee.w;
        }
    }
#pragma unroll
    for (int j = 0; j < CNT; j++) {
        best.x = fmaxf(best.x, acc[j].x);
        best.y = fmaxf(best.y, acc[j].y);
        best.z = fmaxf(best.z, acc[j].z);
        best.w = fmaxf(best.w, acc[j].w);
    }
}

// ---------------- fused y-kernel (decode step S); 128 thr, v-split x2 ----------------
__global__ __launch_bounds__(128) void fused_y(const float* __restrict__ cc,
                                               const float* __restrict__ u,
                                               const float* __restrict__ Dskip,
                                               const float* __restrict__ dtp,
                                               int S, float* __restrict__ ymax)
{
    __shared__ float Bs[4][16], Cs[4][16];
    __shared__ float Gs[4][NV][MAXS];
    __shared__ float G0[4];
    __shared__ float4 sb1[4][16];
    const int tid = threadIdx.x;
    const int hf = tid >> 6;
    const int t64 = tid & 63;
    const int pl = t64 >> 4, dq = t64 & 15;
    const int p0 = blockIdx.x * 4;
    const int p = p0 + pl;
    const int h = p >> 5, w = p & 31;
    const int slotS = S - 1;
    const float dti = dtp[0];

    float4 dc = *(const float4*)&cc[p * 96 + dq * 4];
    float4 dl4;
    dl4.x = sp_f(dc.x + dti); dl4.y = sp_f(dc.y + dti);
    dl4.z = sp_f(dc.z + dti); dl4.w = sp_f(dc.w + dti);
    float4 a4  = *(const float4*)&g_A[dq * 4];
    float4 ra4 = *(const float4*)&g_rA[dq * 4];
    float4 e4o, f4o;
    e4o.x = __expf(dl4.x * a4.x); e4o.y = __expf(dl4.y * a4.y);
    e4o.z = __expf(dl4.z * a4.z); e4o.w = __expf(dl4.w * a4.w);
    float4 u4 = *(const float4*)&u[p * 64 + dq * 4];
    f4o.x = (e4o.x - 1.f) * ra4.x * u4.x;
    f4o.y = (e4o.y - 1.f) * ra4.y * u4.y;
    f4o.z = (e4o.z - 1.f) * ra4.z * u4.z;
    f4o.w = (e4o.w - 1.f) * ra4.w * u4.w;

    if (hf == 0) {
        float4* efp = (float4*)g_ef + (((size_t)slotS * HW + p) * 16 + dq) * 2;
        efp[0] = e4o; efp[1] = f4o;
        if (!g_uniA) {
            *(float4*)&g_dl[((size_t)slotS * HW + p) * 64 + dq * 4] = dl4;
            *(float4*)&g_uf[((size_t)slotS * HW + p) * 64 + dq * 4] = u4;
        }
        float bv = cc[p * 96 + 64 + dq];
        g_Bf[((size_t)slotS * HW + p) * 16 + dq] = bv;
        Bs[pl][dq] = bv;
        Cs[pl][dq] = cc[p * 96 + 80 + dq];
    }
    __syncthreads();

    if (tid < 4) {
        float s = 0.f;
#pragma unroll
        for (int n = 0; n < 16; n++) s += Bs[tid][n] * Cs[tid][n];
        G0[tid] = s;
    }
    const int Sm1 = S - 1;
    const int tot = 4 * NV * Sm1;
    for (int idx = tid; idx < tot; idx += 128) {
        int i = idx / (NV * Sm1);
        int rem = idx - i * (NV * Sm1);
        int v = rem / Sm1;
        int k = rem - v * Sm1 + 1;
        int vx = v / 5 - 2, vy = v % 5 - 2;
        int pp = p0 + i;
        int hh = ((pp >> 5) + k * vy) & 31;
        int ww = ((pp & 31) + k * vx) & 31;
        int x = (hh << 5) + ww;
        const float* bp = &g_Bf[((size_t)(S - 1 - k) * HW + x) * 16];
        float s = 0.f;
#pragma unroll
        for (int n = 0; n < 16; n++) s += bp[n] * Cs[i][n];
        Gs[i][v][k] = s;
    }
    __syncthreads();

    float4 best = {-3e38f, -3e38f, -3e38f, -3e38f};
    if (g_uniA) {
        const float g0 = G0[pl];
        const float* GsRow = &Gs[pl][0][0];
        if (hf == 0) {
            yv_chunk<4>(0, S, h, w, dq, GsRow, g0, e4o, f4o, best);
            yv_chunk<4>(4, S, h, w, dq, GsRow, g0, e4o, f4o, best);
            yv_chunk<4>(8, S, h, w, dq, GsRow, g0, e4o, f4o, best);
        } else {
            yv_chunk<4>(12, S, h, w, dq, GsRow, g0, e4o, f4o, best);
            yv_chunk<4>(16, S, h, w, dq, GsRow, g0, e4o, f4o, best);
            yv_chunk<5>(20, S, h, w, dq, GsRow, g0, e4o, f4o, best);
        }
    } else if (hf == 0) {
        // generic A fallback (correct for any A; half 0 covers all 25 v)
#pragma unroll 1
        for (int v = 0; v < NV; v++) {
            int vx = v / 5 - 2, vy = v % 5 - 2;
            float4 accv = {0.f, 0.f, 0.f, 0.f};
#pragma unroll 1
            for (int n = 0; n < 16; n++) {
                float4 an4 = *(const float4*)&g_A[n * 64 + dq * 4];
                float4 rn4 = *(const float4*)&g_rA[n * 64 + dq * 4];
                float C = Cs[pl][n];
                float4 e0;
                e0.x = __expf(dl4.x * an4.x); e0.y = __expf(dl4.y * an4.y);
                e0.z = __expf(dl4.z * an4.z); e0.w = __expf(dl4.w * an4.w);
                float bc = Bs[pl][n] * C;
                float4 P = e0, a4c;
                a4c.x = (e0.x - 1.f) * rn4.x * u4.x * bc;
                a4c.y = (e0.y - 1.f) * rn4.y * u4.y * bc;
                a4c.z = (e0.z - 1.f) * rn4.z * u4.z * bc;
                a4c.w = (e0.w - 1.f) * rn4.w * u4.w * bc;
                for (int k = 1; k < S; k++) {
                    int hh = (h + k * vy) & 31;
                    int ww = (w + k * vx) & 31;
                    int x = (hh << 5) + ww;
                    int sl = S - 1 - k;
                    float4 dl = *(const float4*)&g_dl[((size_t)sl * HW + x) * 64 + dq * 4];
                    float4 uu = *(const float4*)&g_uf[((size_t)sl * HW + x) * 64 + dq * 4];
                    float Bt = g_Bf[((size_t)sl * HW + x) * 16 + n] * C;
                    float4 ee;
                    ee.x = __expf(dl.x * an4.x); ee.y = __expf(dl.y * an4.y);
                    ee.z = __expf(dl.z * an4.z); ee.w = __expf(dl.w * an4.w);
                    a4c.x = fmaf(P.x * (ee.x - 1.f) * rn4.x * uu.x, Bt, a4c.x);
                    a4c.y = fmaf(P.y * (ee.y - 1.f) * rn4.y * uu.y, Bt, a4c.y);
                    a4c.z = fmaf(P.z * (ee.z - 1.f) * rn4.z * uu.z, Bt, a4c.z);
                    a4c.w = fmaf(P.w * (ee.w - 1.f) * rn4.w * uu.w, Bt, a4c.w);
                    P.x *= ee.x; P.y *= ee.y; P.z *= ee.z; P.w *= ee.w;
                }
                accv.x += a4c.x; accv.y += a4c.y; accv.z += a4c.z; accv.w += a4c.w;
            }
            best.x = fmaxf(best.x, accv.x);
            best.y = fmaxf(best.y, accv.y);
            best.z = fmaxf(best.z, accv.z);
            best.w = fmaxf(best.w, accv.w);
        }
    }

    if (hf == 1) sb1[pl][dq] = best;
    __syncthreads();
    if (hf == 0) {
        float4 b1 = sb1[pl][dq];
        best.x = fmaxf(best.x, b1.x);
        best.y = fmaxf(best.y, b1.y);
        best.z = fmaxf(best.z, b1.z);
        best.w = fmaxf(best.w, b1.w);
        float4 dk = *(const float4*)&Dskip[dq * 4];
        float4 o;
        o.x = fmaf(dk.x, u4.x, best.x);
        o.y = fmaf(dk.y, u4.y, best.y);
        o.z = fmaf(dk.z, u4.z, best.z);
        o.w = fmaf(dk.w, u4.w, best.w);
        *(float4*)&ymax[p * 64 + dq * 4] = o;
    }
}

// ---------------- launch ----------------
extern "C" void kernel_launch(void* const* d_in, const int* in_sizes, int n_in,
                              void* d_out, int out_size)
{
    const float* input_seq = (const float*)d_in[0];
    const float* enc_w1 = (const float*)d_in[1];
    const float* enc_b1 = (const float*)d_in[2];
    const float* enc_w2 = (const float*)d_in[3];
    const float* enc_b2 = (const float*)d_in[4];
    const float* wd     = (const float*)d_in[5];
    const float* bd     = (const float*)d_in[6];
    const float* wB     = (const float*)d_in[7];
    const float* wC     = (const float*)d_in[8];
    const float* logA   = (const float*)d_in[9];
    const float* Dskip  = (const float*)d_in[10];
    const float* dt_inv = (const float*)d_in[11];
    const float* dec_w1 = (const float*)d_in[12];
    const float* dec_b1 = (const float*)d_in[13];
    const float* dec_w2 = (const float*)d_in[14];
    const float* dec_b2 = (const float*)d_in[15];
    const float* dec_w3 = (const float*)d_in[16];
    const float* dec_b3 = (const float*)d_in[17];
    float* out = (float*)d_out;

    float *p_u, *p_e1, *p_cc, *p_wt96, *p_wtE, *p_wtD1, *p_wtD2, *p_bpack;
    float *p_ymax, *p_d1, *p_d2;
    cudaGetSymbolAddress((void**)&p_u, g_u);
    cudaGetSymbolAddress((void**)&p_e1, g_e1);
    cudaGetSymbolAddress((void**)&p_cc, g_cc);
    cudaGetSymbolAddress((void**)&p_wt96, g_wt96);
    cudaGetSymbolAddress((void**)&p_wtE, g_wtE);
    cudaGetSymbolAddress((void**)&p_wtD1, g_wtD1);
    cudaGetSymbolAddress((void**)&p_wtD2, g_wtD2);
    cudaGetSymbolAddress((void**)&p_bpack, g_bpack);
    cudaGetSymbolAddress((void**)&p_ymax, g_ymax);
    cudaGetSymbolAddress((void**)&p_d1, g_d1);
    cudaGetSymbolAddress((void**)&p_d2, g_d2);

    const int XS_BYTES = 6 * 32 * 17 * 16;   // 52224
    cudaFuncSetAttribute(conv_f4w<true>,  cudaFuncAttributeMaxDynamicSharedMemorySize, XS_BYTES);
    cudaFuncSetAttribute(conv_f4w<false>, cudaFuncAttributeMaxDynamicSharedMemorySize, XS_BYTES);
    cudaFuncSetAttribute(conv_f4q<true>,  cudaFuncAttributeMaxDynamicSharedMemorySize, XS_BYTES);
    cudaFuncSetAttribute(conv_f4q<false>, cudaFuncAttributeMaxDynamicSharedMemorySize, XS_BYTES);

    pack_all<<<648, 256>>>(wd, bd, wB, wC, logA, enc_w2, dec_w1, dec_w2);
    check_uni<<<1, 256>>>(logA);

    // ---- encode: batched over 4 frames ----
    conv1_cl<<<dim3(8, 16, TIN), 128>>>(input_seq, enc_w1, enc_b1, p_e1);
    conv_f4w<true><<<dim3(8, 8, TIN), 256, XS_BYTES>>>(p_e1, p_wtE, enc_b2, p_u, DM);
    conv_f4w<false><<<dim3(8, 12, TIN), 256, XS_BYTES>>>(p_u, p_wt96, p_bpack, p_cc, 96);
    prep<<<dim3(128, 1, TIN), 128>>>(p_cc, p_u, dt_inv);

    // ---- decode ----
    int steps = out_size / HW;
    for (int t = 0; t < steps; t++) {
        const float* src = (t == 0) ? (input_seq + 3 * HW) : (out + (size_t)(t - 1) * HW);
        conv1_cl<<<dim3(8, 16, 1), 128>>>(src, enc_w1, enc_b1, p_e1);
        conv_f4q<true><<<dim3(8, 16, 1), 256, XS_BYTES>>>(p_e1, p_wtE, enc_b2, p_u, DM);
        conv_f4q<false><<<dim3(8, 24, 1), 256, XS_BYTES>>>(p_u, p_wt96, p_bpack, p_cc, 96);
        fused_y<<<256, 128>>>(p_cc, p_u, Dskip, dt_inv, TIN + 1 + t, p_ymax);
        conv_f4q<true><<<dim3(8, 16, 1), 256, XS_BYTES>>>(p_ymax, p_wtD1, dec_b1, p_d1, DM);
        conv_f4q<true><<<dim3(8, 16, 1), 256, XS_BYTES>>>(p_d1, p_wtD2, dec_b2, p_d2, DM);
        conv_out<<<64, 128>>>(p_d2, dec_w3, dec_b3, out + (size_t)t * HW);
    }
}